// round 15
// baseline (speedup 1.0000x reference)
#include <cuda_runtime.h>
#include <cuda_fp16.h>
#include <math_constants.h>
#include <cstdint>

#define ROWS_TOTAL 16384
#define DIM 1024
#define CDIM 256
#define NCODES 8192
#define NCAND  8                     // exact-rescore candidate count per row

__device__ float g_h[ROWS_TOTAL * CDIM];            // normalized projections (fp32, rescore)
__device__ float g_hcsq[NCODES];                    // 0.5*||c||^2
__device__ float g_hscale[ROWS_TOTAL];              // per-row h dequant scale (max/127)
__device__ float g_cscale[NCODES];                  // per-code cb dequant scale (max/127)
__device__ __align__(16) signed char g_hi8[ROWS_TOTAL * CDIM];  // h int8 (argmin A)
__device__ __align__(16) signed char g_ci8[NCODES * CDIM];      // codebook int8 (argmin B)
__device__ __half g_xh[ROWS_TOTAL * DIM];           // x fp16 hi
__device__ __half g_xl[ROWS_TOTAL * DIM];           // x fp16 lo
__device__ __half g_Wh[CDIM * DIM];                 // W fp16 hi
__device__ __half g_Wl[CDIM * DIM];                 // W fp16 lo
__device__ int g_cand[ROWS_TOTAL * NCAND];          // top-8 candidates per row

// ---------------- helpers ----------------
__device__ __forceinline__ void cp16(void* sdst, const void* gsrc) {
    unsigned s = (unsigned)__cvta_generic_to_shared(sdst);
    asm volatile("cp.async.cg.shared.global [%0], [%1], 16;\n" :: "r"(s), "l"(gsrc) : "memory");
}
#define CP_COMMIT() asm volatile("cp.async.commit_group;\n" ::: "memory")
#define CP_WAIT0()  asm volatile("cp.async.wait_group 0;\n" ::: "memory")

__device__ __forceinline__ uint32_t smem_u32(const void* p) {
    uint32_t a;
    asm("{ .reg .u64 t; cvta.to.shared.u64 t, %1; cvt.u32.u64 %0, t; }" : "=r"(a) : "l"(p));
    return a;
}
__device__ __forceinline__ void ldsm_x4(uint32_t* r, uint32_t addr) {
    asm volatile("ldmatrix.sync.aligned.m8n8.x4.shared.b16 {%0,%1,%2,%3}, [%4];"
                 : "=r"(r[0]), "=r"(r[1]), "=r"(r[2]), "=r"(r[3]) : "r"(addr));
}
__device__ __forceinline__ void mma16816h(float* d, const uint32_t* a, const uint32_t* b) {
    asm volatile("mma.sync.aligned.m16n8k16.row.col.f32.f16.f16.f32 "
                 "{%0,%1,%2,%3}, {%4,%5,%6,%7}, {%8,%9}, {%0,%1,%2,%3};"
                 : "+f"(d[0]), "+f"(d[1]), "+f"(d[2]), "+f"(d[3])
                 : "r"(a[0]), "r"(a[1]), "r"(a[2]), "r"(a[3]), "r"(b[0]), "r"(b[1]));
}
__device__ __forceinline__ void mma16832s8(int* d, const uint32_t* a, const uint32_t* b) {
    asm volatile("mma.sync.aligned.m16n8k32.row.col.s32.s8.s8.s32 "
                 "{%0,%1,%2,%3}, {%4,%5,%6,%7}, {%8,%9}, {%0,%1,%2,%3};"
                 : "+r"(d[0]), "+r"(d[1]), "+r"(d[2]), "+r"(d[3])
                 : "r"(a[0]), "r"(a[1]), "r"(a[2]), "r"(a[3]), "r"(b[0]), "r"(b[1]));
}
__device__ __forceinline__ int q8s(float v, float scale) {
    int q = __float2int_rn(v * scale);
    return min(127, max(-127, q));
}

// ---------------------------------------------------------------------------
// Kernel 1 (fused prep): x split | W split | codebook int8 (per-code scale)
//                        + 0.5||c||^2 + g_cscale
// ---------------------------------------------------------------------------
__device__ __forceinline__ void split4(const float* src, __half* dh, __half* dl, int i) {
    float4 v = *(const float4*)(src + i);
    __half h0 = __float2half_rn(v.x), h1 = __float2half_rn(v.y);
    __half h2 = __float2half_rn(v.z), h3 = __float2half_rn(v.w);
    *(__half2*)(dh + i)     = __halves2half2(h0, h1);
    *(__half2*)(dh + i + 2) = __halves2half2(h2, h3);
    *(__half2*)(dl + i)     = __floats2half2_rn(v.x - __half2float(h0), v.y - __half2float(h1));
    *(__half2*)(dl + i + 2) = __floats2half2_rn(v.z - __half2float(h2), v.w - __half2float(h3));
}
__global__ void __launch_bounds__(256) prep_kernel(const float* __restrict__ x,
                                                   const float* __restrict__ W,
                                                   const float* __restrict__ cb) {
    int b = blockIdx.x;
    if (b < 16384) { split4(x, g_xh, g_xl, (b * 256 + threadIdx.x) * 4); return; }
    b -= 16384;
    if (b < 256)   { split4(W, g_Wh, g_Wl, (b * 256 + threadIdx.x) * 4); return; }
    b -= 256;
    int warp = threadIdx.x >> 5, lane = threadIdx.x & 31;
    int row = b * 8 + warp;
    const float* p = cb + (size_t)row * CDIM + lane * 8;
    float4 v0 = *(const float4*)(p);
    float4 v1 = *(const float4*)(p + 4);
    float vv[8] = { v0.x, v0.y, v0.z, v0.w, v1.x, v1.y, v1.z, v1.w };
    float s = 0.f, m = 0.f;
#pragma unroll
    for (int j = 0; j < 8; ++j) { s = fmaf(vv[j], vv[j], s); m = fmaxf(m, fabsf(vv[j])); }
#pragma unroll
    for (int o = 16; o; o >>= 1) {
        s += __shfl_xor_sync(0xffffffffu, s, o);
        m = fmaxf(m, __shfl_xor_sync(0xffffffffu, m, o));
    }
    float scale = 127.0f / m;                     // m >= |any element| > 0 (random data)
    unsigned long long pk = 0;
#pragma unroll
    for (int j = 0; j < 8; ++j)
        pk |= (unsigned long long)(unsigned char)(signed char)q8s(vv[j], scale) << (8 * j);
    *(unsigned long long*)(g_ci8 + (size_t)row * CDIM + lane * 8) = pk;
    if (lane == 0) { g_hcsq[row] = 0.5f * s; g_cscale[row] = m * (1.0f / 127.0f); }
}

// ---------------------------------------------------------------------------
// Kernel 2: h = LayerNorm(x @ W^T) via fp16 3-term tensor MMA; emits fp32 h
// + per-row-scaled int8 h + g_hscale.
// ---------------------------------------------------------------------------
#define G1_PITCH 144
#define G1_ASP   18432
#define G1_ABUF  36864
#define G1_BOFF  73728
#define G1_BSP   36864
#define G1_BBUF  73728
#define G1_SM    221184

__global__ void __launch_bounds__(512, 1) gemm1_mma_kernel() {
    extern __shared__ __align__(1024) char smem[];
    uint32_t sb = smem_u32(smem);
    int tid = threadIdx.x, lane = tid & 31, warp = tid >> 5;
    int row0 = blockIdx.x * 128;
    int wr = warp & 3, wc = warp >> 2;

    auto prefetch = [&](int kc, int buf) {
        const __half* xs[2] = { g_xh, g_xl };
        for (int i = tid; i < 2048; i += 512) {
            int sp = i >> 10, idx = i & 1023, r = idx >> 3, j = idx & 7;
            cp16(smem + buf * G1_ABUF + sp * G1_ASP + r * G1_PITCH + j * 16,
                 xs[sp] + (size_t)(row0 + r) * DIM + kc * 64 + j * 8);
        }
        const __half* ws[2] = { g_Wh, g_Wl };
        for (int i = tid; i < 4096; i += 512) {
            int sp = i >> 11, idx = i & 2047, c = idx >> 3, j = idx & 7;
            cp16(smem + G1_BOFF + buf * G1_BBUF + sp * G1_BSP + c * G1_PITCH + j * 16,
                 ws[sp] + (size_t)c * DIM + kc * 64 + j * 8);
        }
    };

    prefetch(0, 0);
    CP_COMMIT();

    uint32_t a_addr = sb + (uint32_t)(wr * 32 + (lane & 7) + 8 * ((lane >> 3) & 1)) * G1_PITCH
                         + (uint32_t)(lane >> 4) * 16;
    uint32_t b_addr = sb + G1_BOFF + (uint32_t)(wc * 64 + (lane & 7) + 8 * (lane >> 4)) * G1_PITCH
                         + (uint32_t)((lane >> 3) & 1) * 16;

    float acc[2][8][4];
#pragma unroll
    for (int mt = 0; mt < 2; ++mt)
#pragma unroll
        for (int nt = 0; nt < 8; ++nt)
#pragma unroll
            for (int r = 0; r < 4; ++r) acc[mt][nt][r] = 0.f;

    for (int kc = 0; kc < 16; ++kc) {
        CP_WAIT0();
        __syncthreads();
        if (kc + 1 < 16) { prefetch(kc + 1, (kc + 1) & 1); CP_COMMIT(); }

        uint32_t ab = a_addr + (kc & 1) * G1_ABUF;
        uint32_t bb = b_addr + (kc & 1) * G1_BBUF;
#pragma unroll
        for (int ks = 0; ks < 4; ++ks) {
            uint32_t a[2][2][4];
#pragma unroll
            for (int mt = 0; mt < 2; ++mt)
#pragma unroll
                for (int sp = 0; sp < 2; ++sp)
                    ldsm_x4(a[mt][sp], ab + mt * (16 * G1_PITCH) + sp * G1_ASP + ks * 32);
#pragma unroll
            for (int np = 0; np < 4; ++np) {
                uint32_t bh[4], bl[4];
                ldsm_x4(bh, bb + np * (16 * G1_PITCH) + ks * 32);
                ldsm_x4(bl, bb + np * (16 * G1_PITCH) + G1_BSP + ks * 32);
#pragma unroll
                for (int mt = 0; mt < 2; ++mt)
#pragma unroll
                    for (int nn = 0; nn < 2; ++nn) {
                        int nt = np * 2 + nn;
                        mma16816h(acc[mt][nt], a[mt][0], &bh[nn * 2]);   // xh*Wh
                        mma16816h(acc[mt][nt], a[mt][1], &bh[nn * 2]);   // xl*Wh
                        mma16816h(acc[mt][nt], a[mt][0], &bl[nn * 2]);   // xh*Wl
                    }
            }
        }
    }

    // ---- LN epilogue ----
    __syncthreads();
    float* sS = (float*)smem;                        // [128 rows][4 wc]
    float* sQ = (float*)(smem + 2048);
    float* sM = (float*)(smem + 4096);               // row-max staging

    // stage 1: row sums / sumsq
#pragma unroll
    for (int mt = 0; mt < 2; ++mt)
#pragma unroll
        for (int rr = 0; rr < 2; ++rr) {
            float s = 0.f, q = 0.f;
#pragma unroll
            for (int nt = 0; nt < 8; ++nt)
#pragma unroll
                for (int e = 0; e < 2; ++e) {
                    float v = acc[mt][nt][rr * 2 + e];
                    s += v; q = fmaf(v, v, q);
                }
            s += __shfl_xor_sync(0xffffffffu, s, 1); s += __shfl_xor_sync(0xffffffffu, s, 2);
            q += __shfl_xor_sync(0xffffffffu, q, 1); q += __shfl_xor_sync(0xffffffffu, q, 2);
            int row_l = wr * 32 + mt * 16 + rr * 8 + (lane >> 2);
            if ((lane & 3) == 0) { sS[row_l * 4 + wc] = s; sQ[row_l * 4 + wc] = q; }
        }
    __syncthreads();

    // stage 2a: per-row max |normalized value|
#pragma unroll
    for (int mt = 0; mt < 2; ++mt)
#pragma unroll
        for (int rr = 0; rr < 2; ++rr) {
            int row_l = wr * 32 + mt * 16 + rr * 8 + (lane >> 2);
            float s = sS[row_l * 4] + sS[row_l * 4 + 1] + sS[row_l * 4 + 2] + sS[row_l * 4 + 3];
            float q = sQ[row_l * 4] + sQ[row_l * 4 + 1] + sQ[row_l * 4 + 2] + sQ[row_l * 4 + 3];
            float mean = s * (1.f / CDIM);
            float var  = q * (1.f / CDIM) - mean * mean;
            float rstd = rsqrtf(var + 1e-5f);
            float vm = 0.f;
#pragma unroll
            for (int nt = 0; nt < 8; ++nt)
#pragma unroll
                for (int e = 0; e < 2; ++e)
                    vm = fmaxf(vm, fabsf((acc[mt][nt][rr * 2 + e] - mean) * rstd));
            vm = fmaxf(vm, __shfl_xor_sync(0xffffffffu, vm, 1));
            vm = fmaxf(vm, __shfl_xor_sync(0xffffffffu, vm, 2));
            if ((lane & 3) == 0) sM[row_l * 4 + wc] = vm;
        }
    __syncthreads();

    // stage 2b: normalize, quantize with per-row scale, emit
#pragma unroll
    for (int mt = 0; mt < 2; ++mt)
#pragma unroll
        for (int rr = 0; rr < 2; ++rr) {
            int row_l = wr * 32 + mt * 16 + rr * 8 + (lane >> 2);
            float s = sS[row_l * 4] + sS[row_l * 4 + 1] + sS[row_l * 4 + 2] + sS[row_l * 4 + 3];
            float q = sQ[row_l * 4] + sQ[row_l * 4 + 1] + sQ[row_l * 4 + 2] + sQ[row_l * 4 + 3];
            float mean = s * (1.f / CDIM);
            float var  = q * (1.f / CDIM) - mean * mean;
            float rstd = rsqrtf(var + 1e-5f);
            float vmax = fmaxf(fmaxf(sM[row_l * 4], sM[row_l * 4 + 1]),
                               fmaxf(sM[row_l * 4 + 2], sM[row_l * 4 + 3]));
            float hsc = 127.0f / vmax;
            size_t row = (size_t)(row0 + row_l);
            if (wc == 0 && (lane & 3) == 0) g_hscale[row] = vmax * (1.0f / 127.0f);
#pragma unroll
            for (int nt = 0; nt < 8; ++nt) {
                float v0 = (acc[mt][nt][rr * 2 + 0] - mean) * rstd;
                float v1 = (acc[mt][nt][rr * 2 + 1] - mean) * rstd;
                size_t col = wc * 64 + nt * 8 + (lane & 3) * 2;
                *(float2*)(g_h + row * CDIM + col) = make_float2(v0, v1);
                int q0 = q8s(v0, hsc), q1 = q8s(v1, hsc);
                *(unsigned short*)(g_hi8 + row * CDIM + col) =
                    (unsigned short)(((unsigned)(unsigned char)(signed char)q0) |
                                     ((unsigned)(unsigned char)(signed char)q1 << 8));
            }
        }
}

// ---------------------------------------------------------------------------
// Kernel 3: int8 IMMA (m16n8k32) distance GEMM + per-row top-8 candidates.
// dist = 0.5||c_k||^2 - (acc * hscale_row) * cscale_k
// ---------------------------------------------------------------------------
#define PITCH    272
#define B_OFF    34816
#define BBUF     34816
#define CSQ_OFF  104448
#define CSC_OFF  105472
#define SM_TOTAL 106496
#define RED_OFF  34816

__global__ void __launch_bounds__(256, 1) mma_argmin_kernel() {
    extern __shared__ __align__(1024) char smem[];
    uint32_t sb = smem_u32(smem);
    float* csq_s = (float*)(smem + CSQ_OFF);
    float* csc_s = (float*)(smem + CSC_OFF);
    int tid = threadIdx.x, lane = tid & 31, warp = tid >> 5;
    int row0 = blockIdx.x * 128;

    for (int i = tid; i < 2048; i += 256) {
        int r = i >> 4, j = i & 15;
        cp16(smem + r * PITCH + j * 16, g_hi8 + (size_t)(row0 + r) * CDIM + j * 16);
    }
    for (int i = tid; i < 2048; i += 256) {
        int r = i >> 4, j = i & 15;
        cp16(smem + B_OFF + r * PITCH + j * 16, g_ci8 + (size_t)r * CDIM + j * 16);
    }
    if (tid < 32) {
        cp16((char*)csq_s + tid * 16, g_hcsq + tid * 4);
        cp16((char*)csc_s + tid * 16, g_cscale + tid * 4);
    }
    CP_COMMIT();

    int mrow0 = (warp & 1) * 64;
    int ncol0 = (warp >> 1) * 32;
    uint32_t a_addr = sb + (uint32_t)(mrow0 + (lane & 7) + 8 * ((lane >> 3) & 1)) * PITCH
                         + (uint32_t)(lane >> 4) * 16;
    uint32_t b_addr = sb + B_OFF + (uint32_t)(ncol0 + (lane & 7) + 8 * (lane >> 4)) * PITCH
                         + (uint32_t)((lane >> 3) & 1) * 16;

    // per-accumulator-slot h dequant scale (8 rows per thread)
    float hs[8];
#pragma unroll
    for (int s = 0; s < 8; ++s) {
        int row_l = mrow0 + (s >> 1) * 16 + (s & 1) * 8 + (lane >> 2);
        hs[s] = g_hscale[row0 + row_l];
    }

    float best1[8], best2[8]; int id1[8], id2[8];
#pragma unroll
    for (int s = 0; s < 8; ++s) { best1[s] = CUDART_INF_F; best2[s] = CUDART_INF_F; id1[s] = 0; id2[s] = 0; }

    for (int t = 0; t < 64; ++t) {
        CP_WAIT0();
        __syncthreads();

        if (t + 1 < 64) {
            int c0 = (t + 1) * 128;
            char* buf = smem + B_OFF + ((t + 1) & 1) * BBUF;
            for (int i = tid; i < 2048; i += 256) {
                int r = i >> 4, j = i & 15;
                cp16(buf + r * PITCH + j * 16, g_ci8 + (size_t)(c0 + r) * CDIM + j * 16);
            }
            if (tid < 32) {
                cp16((char*)csq_s + ((t + 1) & 1) * 512 + tid * 16, g_hcsq + c0 + tid * 4);
                cp16((char*)csc_s + ((t + 1) & 1) * 512 + tid * 16, g_cscale + c0 + tid * 4);
            }
            CP_COMMIT();
        }

        int acc[4][4][4];
#pragma unroll
        for (int mt = 0; mt < 4; ++mt)
#pragma unroll
            for (int nt = 0; nt < 4; ++nt)
#pragma unroll
                for (int r = 0; r < 4; ++r) acc[mt][nt][r] = 0;

        uint32_t bb = b_addr + (t & 1) * BBUF;
#pragma unroll
        for (int ks = 0; ks < 8; ++ks) {
            uint32_t a[4][4], b[2][4];
#pragma unroll
            for (int mt = 0; mt < 4; ++mt)
                ldsm_x4(a[mt], a_addr + mt * (16 * PITCH) + ks * 32);
#pragma unroll
            for (int np = 0; np < 2; ++np)
                ldsm_x4(b[np], bb + np * (16 * PITCH) + ks * 32);
#pragma unroll
            for (int mt = 0; mt < 4; ++mt)
#pragma unroll
                for (int nt = 0; nt < 4; ++nt)
                    mma16832s8(acc[mt][nt], a[mt], &b[nt >> 1][(nt & 1) * 2]);
        }

        const float* qp = csq_s + (t & 1) * 128;
        const float* cp_ = csc_s + (t & 1) * 128;
#pragma unroll
        for (int mt = 0; mt < 4; ++mt)
#pragma unroll
            for (int nt = 0; nt < 4; ++nt) {
                int cin = ncol0 + nt * 8 + (lane & 3) * 2;
#pragma unroll
                for (int r = 0; r < 4; ++r) {
                    int s = mt * 2 + (r >> 1);
                    float f = (float)acc[mt][nt][r] * hs[s];
                    float d = fmaf(-f, cp_[cin + (r & 1)], qp[cin + (r & 1)]);
                    int code = t * 128 + cin + (r & 1);
                    if (d < best1[s]) { best2[s] = best1[s]; id2[s] = id1[s]; best1[s] = d; id1[s] = code; }
                    else if (d < best2[s]) { best2[s] = d; id2[s] = code; }
                }
            }
    }

    // cross-thread reduce: per row, 32 candidates -> top-8
    __syncthreads();
    float* red_d = (float*)(smem + RED_OFF);          // [128][32]
    int*   red_i = (int*)(smem + RED_OFF + 16384);    // [128][32]
#pragma unroll
    for (int s = 0; s < 8; ++s) {
        int row_l = (warp & 1) * 64 + (s >> 1) * 16 + (s & 1) * 8 + (lane >> 2);
        int e = (warp >> 1) * 8 + (lane & 3) * 2;
        red_d[row_l * 32 + e]     = best1[s];  red_i[row_l * 32 + e]     = id1[s];
        red_d[row_l * 32 + e + 1] = best2[s];  red_i[row_l * 32 + e + 1] = id2[s];
    }
    __syncthreads();
    if (tid < 128) {
        float bd[NCAND]; int bi[NCAND];
#pragma unroll
        for (int k = 0; k < NCAND; ++k) { bd[k] = CUDART_INF_F; bi[k] = 0; }
        for (int j = 0; j < 32; ++j) {
            float d = red_d[tid * 32 + j]; int ix = red_i[tid * 32 + j];
#pragma unroll
            for (int k = 0; k < NCAND; ++k) {
                if (d < bd[k] || (d == bd[k] && ix < bi[k])) {
#pragma unroll
                    for (int m = NCAND - 1; m > k; --m) { bd[m] = bd[m - 1]; bi[m] = bi[m - 1]; }
                    bd[k] = d; bi[k] = ix;
                    break;
                }
            }
        }
#pragma unroll
        for (int k = 0; k < NCAND; ++k) g_cand[(row0 + tid) * NCAND + k] = bi[k];
    }
}

// ---------------------------------------------------------------------------
// Kernel 4: exact fp32 rescoring of the top-8 candidates. One warp per row.
// ---------------------------------------------------------------------------
__global__ void __launch_bounds__(256) rescore_kernel(const float* __restrict__ cb,
                                                      float* __restrict__ out) {
    int wid = threadIdx.x >> 5, lane = threadIdx.x & 31;
    int row = blockIdx.x * 8 + wid;
    int c[NCAND];
#pragma unroll
    for (int q = 0; q < NCAND; ++q) c[q] = g_cand[row * NCAND + q];
    const float* hr = g_h + (size_t)row * CDIM;
    float d[NCAND];
#pragma unroll
    for (int q = 0; q < NCAND; ++q) d[q] = 0.f;
#pragma unroll
    for (int j = 0; j < 8; ++j) {
        float hv = hr[lane + 32 * j];
#pragma unroll
        for (int q = 0; q < NCAND; ++q)
            d[q] = fmaf(hv, cb[(size_t)c[q] * CDIM + lane + 32 * j], d[q]);
    }
#pragma unroll
    for (int o = 16; o; o >>= 1)
#pragma unroll
        for (int q = 0; q < NCAND; ++q)
            d[q] += __shfl_xor_sync(0xffffffffu, d[q], o);
    if (lane == 0) {
        float bd = CUDART_INF_F; int bi = 0;
#pragma unroll
        for (int q = 0; q < NCAND; ++q) {
            float dist = g_hcsq[c[q]] - d[q];
            if (dist < bd || (dist == bd && c[q] < bi)) { bd = dist; bi = c[q]; }
        }
        out[row] = (float)bi;                 // float32: harness __output__ dtype
    }
}

// ---------------------------------------------------------------------------
extern "C" void kernel_launch(void* const* d_in, const int* in_sizes, int n_in,
                              void* d_out, int out_size) {
    const float *x = 0, *W = 0, *cbk = 0;
    for (int i = 0; i < n_in; ++i) {
        if      (in_sizes[i] == ROWS_TOTAL * DIM) x   = (const float*)d_in[i];
        else if (in_sizes[i] == CDIM * DIM)       W   = (const float*)d_in[i];
        else if (in_sizes[i] == NCODES * CDIM)    cbk = (const float*)d_in[i];
    }
    float* out = (float*)d_out;
    if (!x || !W || !cbk) return;

    prep_kernel<<<16384 + 256 + 1024, 256>>>(x, W, cbk);

    cudaFuncSetAttribute(gemm1_mma_kernel, cudaFuncAttributeMaxDynamicSharedMemorySize, G1_SM);
    gemm1_mma_kernel<<<ROWS_TOTAL / 128, 512, G1_SM>>>();

    cudaFuncSetAttribute(mma_argmin_kernel, cudaFuncAttributeMaxDynamicSharedMemorySize, SM_TOTAL);
    mma_argmin_kernel<<<ROWS_TOTAL / 128, 256, SM_TOTAL>>>();

    rescore_kernel<<<ROWS_TOTAL / 8, 256>>>(cbk, out);
}

// round 16
// speedup vs baseline: 1.7419x; 1.7419x over previous
#include <cuda_runtime.h>
#include <cuda_fp16.h>
#include <math_constants.h>
#include <cstdint>

#define ROWS_TOTAL 16384
#define DIM 1024
#define CDIM 256
#define NCODES 8192
#define NCAND  8                     // exact-rescore candidate count per row

__device__ float g_h[ROWS_TOTAL * CDIM];            // normalized projections (fp32, rescore)
__device__ float g_hcsq[NCODES];                    // 0.5*||c||^2
__device__ __half g_hf16[ROWS_TOTAL * CDIM];        // h fp16 (argmin A)
__device__ __half g_cf16[NCODES * CDIM];            // codebook fp16 (argmin B)
__device__ __half g_xh[ROWS_TOTAL * DIM];           // x fp16 hi
__device__ __half g_xl[ROWS_TOTAL * DIM];           // x fp16 lo
__device__ __half g_Wh[CDIM * DIM];                 // W fp16 hi
__device__ __half g_Wl[CDIM * DIM];                 // W fp16 lo
__device__ int g_cand[ROWS_TOTAL * NCAND];          // top-8 candidates per row

// ---------------- helpers ----------------
__device__ __forceinline__ void cp16(void* sdst, const void* gsrc) {
    unsigned s = (unsigned)__cvta_generic_to_shared(sdst);
    asm volatile("cp.async.cg.shared.global [%0], [%1], 16;\n" :: "r"(s), "l"(gsrc) : "memory");
}
#define CP_COMMIT() asm volatile("cp.async.commit_group;\n" ::: "memory")
#define CP_WAIT0()  asm volatile("cp.async.wait_group 0;\n" ::: "memory")

__device__ __forceinline__ uint32_t smem_u32(const void* p) {
    uint32_t a;
    asm("{ .reg .u64 t; cvta.to.shared.u64 t, %1; cvt.u32.u64 %0, t; }" : "=r"(a) : "l"(p));
    return a;
}
__device__ __forceinline__ void ldsm_x4(uint32_t* r, uint32_t addr) {
    asm volatile("ldmatrix.sync.aligned.m8n8.x4.shared.b16 {%0,%1,%2,%3}, [%4];"
                 : "=r"(r[0]), "=r"(r[1]), "=r"(r[2]), "=r"(r[3]) : "r"(addr));
}
__device__ __forceinline__ void mma16816h(float* d, const uint32_t* a, const uint32_t* b) {
    asm volatile("mma.sync.aligned.m16n8k16.row.col.f32.f16.f16.f32 "
                 "{%0,%1,%2,%3}, {%4,%5,%6,%7}, {%8,%9}, {%0,%1,%2,%3};"
                 : "+f"(d[0]), "+f"(d[1]), "+f"(d[2]), "+f"(d[3])
                 : "r"(a[0]), "r"(a[1]), "r"(a[2]), "r"(a[3]), "r"(b[0]), "r"(b[1]));
}

// ---------------------------------------------------------------------------
// Kernel 1 (fused prep):
//   blocks [0, 16384)      : x -> fp16 hi/lo split
//   blocks [16384, 16640)  : W -> fp16 hi/lo split
//   blocks [16640, 17664)  : codebook -> fp16 convert + 0.5*||c||^2
// ---------------------------------------------------------------------------
__device__ __forceinline__ void split4(const float* src, __half* dh, __half* dl, int i) {
    float4 v = *(const float4*)(src + i);
    __half h0 = __float2half_rn(v.x), h1 = __float2half_rn(v.y);
    __half h2 = __float2half_rn(v.z), h3 = __float2half_rn(v.w);
    *(__half2*)(dh + i)     = __halves2half2(h0, h1);
    *(__half2*)(dh + i + 2) = __halves2half2(h2, h3);
    *(__half2*)(dl + i)     = __floats2half2_rn(v.x - __half2float(h0), v.y - __half2float(h1));
    *(__half2*)(dl + i + 2) = __floats2half2_rn(v.z - __half2float(h2), v.w - __half2float(h3));
}
__global__ void __launch_bounds__(256) prep_kernel(const float* __restrict__ x,
                                                   const float* __restrict__ W,
                                                   const float* __restrict__ cb) {
    int b = blockIdx.x;
    if (b < 16384) { split4(x, g_xh, g_xl, (b * 256 + threadIdx.x) * 4); return; }
    b -= 16384;
    if (b < 256)   { split4(W, g_Wh, g_Wl, (b * 256 + threadIdx.x) * 4); return; }
    b -= 256;
    // codebook: 8 rows per block, one warp per row; lane handles 8 consecutive cols
    int warp = threadIdx.x >> 5, lane = threadIdx.x & 31;
    int row = b * 8 + warp;
    const float* p = cb + (size_t)row * CDIM + lane * 8;
    float4 v0 = *(const float4*)(p);
    float4 v1 = *(const float4*)(p + 4);
    float s = 0.f;
    s = fmaf(v0.x, v0.x, s); s = fmaf(v0.y, v0.y, s); s = fmaf(v0.z, v0.z, s); s = fmaf(v0.w, v0.w, s);
    s = fmaf(v1.x, v1.x, s); s = fmaf(v1.y, v1.y, s); s = fmaf(v1.z, v1.z, s); s = fmaf(v1.w, v1.w, s);
    __half2 h01 = __floats2half2_rn(v0.x, v0.y);
    __half2 h23 = __floats2half2_rn(v0.z, v0.w);
    __half2 h45 = __floats2half2_rn(v1.x, v1.y);
    __half2 h67 = __floats2half2_rn(v1.z, v1.w);
    uint4 pk;
    pk.x = *(uint32_t*)&h01; pk.y = *(uint32_t*)&h23;
    pk.z = *(uint32_t*)&h45; pk.w = *(uint32_t*)&h67;
    *(uint4*)(g_cf16 + (size_t)row * CDIM + lane * 8) = pk;
#pragma unroll
    for (int o = 16; o; o >>= 1) s += __shfl_xor_sync(0xffffffffu, s, o);
    if (lane == 0) g_hcsq[row] = 0.5f * s;
}

// ---------------------------------------------------------------------------
// Kernel 2: h = LayerNorm(x @ W^T) via fp16 3-term tensor MMA (proven R12).
// Grid 128 (single wave), 512 threads / 16 warps. CTA = 128 rows x 256 cols,
// K=1024 streamed in 16 chunks of 64 (A and B double-buffered).
// dot = xh*Wh + xl*Wh + xh*Wl (fp32 acc); LN fused; emits fp32 h + fp16 h.
// ---------------------------------------------------------------------------
#define G1_PITCH 144
#define G1_ASP   18432
#define G1_ABUF  36864
#define G1_BOFF  73728
#define G1_BSP   36864
#define G1_BBUF  73728
#define G1_SM    221184

__global__ void __launch_bounds__(512, 1) gemm1_mma_kernel() {
    extern __shared__ __align__(1024) char smem[];
    uint32_t sb = smem_u32(smem);
    int tid = threadIdx.x, lane = tid & 31, warp = tid >> 5;
    int row0 = blockIdx.x * 128;
    int wr = warp & 3, wc = warp >> 2;

    auto prefetch = [&](int kc, int buf) {
        const __half* xs[2] = { g_xh, g_xl };
        for (int i = tid; i < 2048; i += 512) {
            int sp = i >> 10, idx = i & 1023, r = idx >> 3, j = idx & 7;
            cp16(smem + buf * G1_ABUF + sp * G1_ASP + r * G1_PITCH + j * 16,
                 xs[sp] + (size_t)(row0 + r) * DIM + kc * 64 + j * 8);
        }
        const __half* ws[2] = { g_Wh, g_Wl };
        for (int i = tid; i < 4096; i += 512) {
            int sp = i >> 11, idx = i & 2047, c = idx >> 3, j = idx & 7;
            cp16(smem + G1_BOFF + buf * G1_BBUF + sp * G1_BSP + c * G1_PITCH + j * 16,
                 ws[sp] + (size_t)c * DIM + kc * 64 + j * 8);
        }
    };

    prefetch(0, 0);
    CP_COMMIT();

    uint32_t a_addr = sb + (uint32_t)(wr * 32 + (lane & 7) + 8 * ((lane >> 3) & 1)) * G1_PITCH
                         + (uint32_t)(lane >> 4) * 16;
    uint32_t b_addr = sb + G1_BOFF + (uint32_t)(wc * 64 + (lane & 7) + 8 * (lane >> 4)) * G1_PITCH
                         + (uint32_t)((lane >> 3) & 1) * 16;

    float acc[2][8][4];
#pragma unroll
    for (int mt = 0; mt < 2; ++mt)
#pragma unroll
        for (int nt = 0; nt < 8; ++nt)
#pragma unroll
            for (int r = 0; r < 4; ++r) acc[mt][nt][r] = 0.f;

    for (int kc = 0; kc < 16; ++kc) {
        CP_WAIT0();
        __syncthreads();
        if (kc + 1 < 16) { prefetch(kc + 1, (kc + 1) & 1); CP_COMMIT(); }

        uint32_t ab = a_addr + (kc & 1) * G1_ABUF;
        uint32_t bb = b_addr + (kc & 1) * G1_BBUF;
#pragma unroll
        for (int ks = 0; ks < 4; ++ks) {
            uint32_t a[2][2][4];
#pragma unroll
            for (int mt = 0; mt < 2; ++mt)
#pragma unroll
                for (int sp = 0; sp < 2; ++sp)
                    ldsm_x4(a[mt][sp], ab + mt * (16 * G1_PITCH) + sp * G1_ASP + ks * 32);
#pragma unroll
            for (int np = 0; np < 4; ++np) {
                uint32_t bh[4], bl[4];
                ldsm_x4(bh, bb + np * (16 * G1_PITCH) + ks * 32);
                ldsm_x4(bl, bb + np * (16 * G1_PITCH) + G1_BSP + ks * 32);
#pragma unroll
                for (int mt = 0; mt < 2; ++mt)
#pragma unroll
                    for (int nn = 0; nn < 2; ++nn) {
                        int nt = np * 2 + nn;
                        mma16816h(acc[mt][nt], a[mt][0], &bh[nn * 2]);   // xh*Wh
                        mma16816h(acc[mt][nt], a[mt][1], &bh[nn * 2]);   // xl*Wh
                        mma16816h(acc[mt][nt], a[mt][0], &bl[nn * 2]);   // xh*Wl
                    }
            }
        }
    }

    // ---- LN epilogue ----
    __syncthreads();
    float* sS = (float*)smem;                        // [128 rows][4 wc]
    float* sQ = (float*)(smem + 2048);

#pragma unroll
    for (int mt = 0; mt < 2; ++mt)
#pragma unroll
        for (int rr = 0; rr < 2; ++rr) {
            float s = 0.f, q = 0.f;
#pragma unroll
            for (int nt = 0; nt < 8; ++nt)
#pragma unroll
                for (int e = 0; e < 2; ++e) {
                    float v = acc[mt][nt][rr * 2 + e];
                    s += v; q = fmaf(v, v, q);
                }
            s += __shfl_xor_sync(0xffffffffu, s, 1); s += __shfl_xor_sync(0xffffffffu, s, 2);
            q += __shfl_xor_sync(0xffffffffu, q, 1); q += __shfl_xor_sync(0xffffffffu, q, 2);
            int row_l = wr * 32 + mt * 16 + rr * 8 + (lane >> 2);
            if ((lane & 3) == 0) { sS[row_l * 4 + wc] = s; sQ[row_l * 4 + wc] = q; }
        }
    __syncthreads();

#pragma unroll
    for (int mt = 0; mt < 2; ++mt)
#pragma unroll
        for (int rr = 0; rr < 2; ++rr) {
            int row_l = wr * 32 + mt * 16 + rr * 8 + (lane >> 2);
            float s = sS[row_l * 4] + sS[row_l * 4 + 1] + sS[row_l * 4 + 2] + sS[row_l * 4 + 3];
            float q = sQ[row_l * 4] + sQ[row_l * 4 + 1] + sQ[row_l * 4 + 2] + sQ[row_l * 4 + 3];
            float mean = s * (1.f / CDIM);
            float var  = q * (1.f / CDIM) - mean * mean;
            float rstd = rsqrtf(var + 1e-5f);
            size_t row = (size_t)(row0 + row_l);
#pragma unroll
            for (int nt = 0; nt < 8; ++nt) {
                float v0 = (acc[mt][nt][rr * 2 + 0] - mean) * rstd;
                float v1 = (acc[mt][nt][rr * 2 + 1] - mean) * rstd;
                size_t col = wc * 64 + nt * 8 + (lane & 3) * 2;
                *(float2*)(g_h + row * CDIM + col) = make_float2(v0, v1);
                *(__half2*)(g_hf16 + row * CDIM + col) = __floats2half2_rn(v0, v1);
            }
        }
}

// ---------------------------------------------------------------------------
// Kernel 3: fp16 single-MMA distance GEMM (proven R11) + per-row top-8.
// Grid 128 (single wave), 256 threads / 8 warps. CTA = 128 rows x all codes,
// streamed in 64 tiles of 128 codes (double-buffered).
// ---------------------------------------------------------------------------
#define PITCH    528
#define B_OFF    67584
#define BBUF     67584
#define CSQ_OFF  202752
#define SM_TOTAL 203776
#define RED_OFF  67584

__global__ void __launch_bounds__(256, 1) mma_argmin_kernel() {
    extern __shared__ __align__(1024) char smem[];
    uint32_t sb = smem_u32(smem);
    float* csq_s = (float*)(smem + CSQ_OFF);
    int tid = threadIdx.x, lane = tid & 31, warp = tid >> 5;
    int row0 = blockIdx.x * 128;

    for (int i = tid; i < 4096; i += 256) {
        int r = i >> 5, j = i & 31;
        cp16(smem + r * PITCH + j * 16, g_hf16 + (size_t)(row0 + r) * CDIM + j * 8);
    }
    for (int i = tid; i < 4096; i += 256) {
        int r = i >> 5, j = i & 31;
        cp16(smem + B_OFF + r * PITCH + j * 16, g_cf16 + (size_t)r * CDIM + j * 8);
    }
    if (tid < 32) cp16((char*)csq_s + tid * 16, g_hcsq + tid * 4);
    CP_COMMIT();

    int mrow0 = (warp & 1) * 64;
    int ncol0 = (warp >> 1) * 32;
    uint32_t a_addr = sb + (uint32_t)(mrow0 + (lane & 7) + 8 * ((lane >> 3) & 1)) * PITCH
                         + (uint32_t)(lane >> 4) * 16;
    uint32_t b_addr = sb + B_OFF + (uint32_t)(ncol0 + (lane & 7) + 8 * (lane >> 4)) * PITCH
                         + (uint32_t)((lane >> 3) & 1) * 16;

    float best1[8], best2[8]; int id1[8], id2[8];
#pragma unroll
    for (int s = 0; s < 8; ++s) { best1[s] = CUDART_INF_F; best2[s] = CUDART_INF_F; id1[s] = 0; id2[s] = 0; }

    for (int t = 0; t < 64; ++t) {
        CP_WAIT0();
        __syncthreads();

        if (t + 1 < 64) {
            int c0 = (t + 1) * 128;
            char* buf = smem + B_OFF + ((t + 1) & 1) * BBUF;
            for (int i = tid; i < 4096; i += 256) {
                int r = i >> 5, j = i & 31;
                cp16(buf + r * PITCH + j * 16, g_cf16 + (size_t)(c0 + r) * CDIM + j * 8);
            }
            if (tid < 32) cp16((char*)csq_s + ((t + 1) & 1) * 512 + tid * 16, g_hcsq + c0 + tid * 4);
            CP_COMMIT();
        }

        float acc[4][4][4];
#pragma unroll
        for (int mt = 0; mt < 4; ++mt)
#pragma unroll
            for (int nt = 0; nt < 4; ++nt)
#pragma unroll
                for (int r = 0; r < 4; ++r) acc[mt][nt][r] = 0.f;

        uint32_t bb = b_addr + (t & 1) * BBUF;
#pragma unroll 4
        for (int ks = 0; ks < 16; ++ks) {
            uint32_t a[4][4], b[2][4];
#pragma unroll
            for (int mt = 0; mt < 4; ++mt)
                ldsm_x4(a[mt], a_addr + mt * (16 * PITCH) + ks * 32);
#pragma unroll
            for (int np = 0; np < 2; ++np)
                ldsm_x4(b[np], bb + np * (16 * PITCH) + ks * 32);
#pragma unroll
            for (int mt = 0; mt < 4; ++mt)
#pragma unroll
                for (int nt = 0; nt < 4; ++nt)
                    mma16816h(acc[mt][nt], a[mt], &b[nt >> 1][(nt & 1) * 2]);
        }

        const float* qp = csq_s + (t & 1) * 128;
#pragma unroll
        for (int mt = 0; mt < 4; ++mt)
#pragma unroll
            for (int nt = 0; nt < 4; ++nt) {
                int cin = ncol0 + nt * 8 + (lane & 3) * 2;
#pragma unroll
                for (int r = 0; r < 4; ++r) {
                    float d = qp[cin + (r & 1)] - acc[mt][nt][r];
                    int code = t * 128 + cin + (r & 1);
                    int s = mt * 2 + (r >> 1);
                    if (d < best1[s]) { best2[s] = best1[s]; id2[s] = id1[s]; best1[s] = d; id1[s] = code; }
                    else if (d < best2[s]) { best2[s] = d; id2[s] = code; }
                }
            }
    }

    // cross-thread reduce: per row, 32 candidates -> top-8
    __syncthreads();
    float* red_d = (float*)(smem + RED_OFF);          // [128][32]
    int*   red_i = (int*)(smem + RED_OFF + 16384);    // [128][32]
#pragma unroll
    for (int s = 0; s < 8; ++s) {
        int row_l = (warp & 1) * 64 + (s >> 1) * 16 + (s & 1) * 8 + (lane >> 2);
        int e = (warp >> 1) * 8 + (lane & 3) * 2;
        red_d[row_l * 32 + e]     = best1[s];  red_i[row_l * 32 + e]     = id1[s];
        red_d[row_l * 32 + e + 1] = best2[s];  red_i[row_l * 32 + e + 1] = id2[s];
    }
    __syncthreads();
    if (tid < 128) {
        float bd[NCAND]; int bi[NCAND];
#pragma unroll
        for (int k = 0; k < NCAND; ++k) { bd[k] = CUDART_INF_F; bi[k] = 0; }
        for (int j = 0; j < 32; ++j) {
            float d = red_d[tid * 32 + j]; int ix = red_i[tid * 32 + j];
#pragma unroll
            for (int k = 0; k < NCAND; ++k) {
                if (d < bd[k] || (d == bd[k] && ix < bi[k])) {
#pragma unroll
                    for (int m = NCAND - 1; m > k; --m) { bd[m] = bd[m - 1]; bi[m] = bi[m - 1]; }
                    bd[k] = d; bi[k] = ix;
                    break;
                }
            }
        }
#pragma unroll
        for (int k = 0; k < NCAND; ++k) g_cand[(row0 + tid) * NCAND + k] = bi[k];
    }
}

// ---------------------------------------------------------------------------
// Kernel 4: exact fp32 rescoring of the top-8 candidates. One warp per row.
// ---------------------------------------------------------------------------
__global__ void __launch_bounds__(256) rescore_kernel(const float* __restrict__ cb,
                                                      float* __restrict__ out) {
    int wid = threadIdx.x >> 5, lane = threadIdx.x & 31;
    int row = blockIdx.x * 8 + wid;
    int c[NCAND];
#pragma unroll
    for (int q = 0; q < NCAND; ++q) c[q] = g_cand[row * NCAND + q];
    const float* hr = g_h + (size_t)row * CDIM;
    float d[NCAND];
#pragma unroll
    for (int q = 0; q < NCAND; ++q) d[q] = 0.f;
#pragma unroll
    for (int j = 0; j < 8; ++j) {
        float hv = hr[lane + 32 * j];
#pragma unroll
        for (int q = 0; q < NCAND; ++q)
            d[q] = fmaf(hv, cb[(size_t)c[q] * CDIM + lane + 32 * j], d[q]);
    }
#pragma unroll
    for (int o = 16; o; o >>= 1)
#pragma unroll
        for (int q = 0; q < NCAND; ++q)
            d[q] += __shfl_xor_sync(0xffffffffu, d[q], o);
    if (lane == 0) {
        float bd = CUDART_INF_F; int bi = 0;
#pragma unroll
        for (int q = 0; q < NCAND; ++q) {
            float dist = g_hcsq[c[q]] - d[q];
            if (dist < bd || (dist == bd && c[q] < bi)) { bd = dist; bi = c[q]; }
        }
        out[row] = (float)bi;                 // float32: harness __output__ dtype
    }
}

// ---------------------------------------------------------------------------
extern "C" void kernel_launch(void* const* d_in, const int* in_sizes, int n_in,
                              void* d_out, int out_size) {
    const float *x = 0, *W = 0, *cbk = 0;
    for (int i = 0; i < n_in; ++i) {
        if      (in_sizes[i] == ROWS_TOTAL * DIM) x   = (const float*)d_in[i];
        else if (in_sizes[i] == CDIM * DIM)       W   = (const float*)d_in[i];
        else if (in_sizes[i] == NCODES * CDIM)    cbk = (const float*)d_in[i];
    }
    float* out = (float*)d_out;
    if (!x || !W || !cbk) return;

    // fused prep: x-split (16384) + W-split (256) + cb fp16/csq (1024)
    prep_kernel<<<16384 + 256 + 1024, 256>>>(x, W, cbk);

    cudaFuncSetAttribute(gemm1_mma_kernel, cudaFuncAttributeMaxDynamicSharedMemorySize, G1_SM);
    gemm1_mma_kernel<<<ROWS_TOTAL / 128, 512, G1_SM>>>();

    cudaFuncSetAttribute(mma_argmin_kernel, cudaFuncAttributeMaxDynamicSharedMemorySize, SM_TOTAL);
    mma_argmin_kernel<<<ROWS_TOTAL / 128, 256, SM_TOTAL>>>();

    rescore_kernel<<<ROWS_TOTAL / 8, 256>>>(cbk, out);
}